// round 17
// baseline (speedup 1.0000x reference)
#include <cuda_runtime.h>
#include <math.h>

#define BATCH 8
#define NA    261888
#define KTOP  6000
#define PROP  1000
#define SHIFT 14
#define NBUCK (1 << 18)
#define CAP   8192
#define SORTN 8192
#define SEGP  1024

#define SLOTS    32
#define SPILLCAP 32768

#define CELLG    16
#define NCELL    (CELLG * CELLG)
#define CELLCAP  768

#define NBLK 148
#define NTHR 256

typedef unsigned long long ull;

/* ---------------- device scratch (static: no allocation allowed) -------- */
__device__ unsigned int       g_hist[BATCH][NBUCK];
__device__ unsigned int       g_base[BATCH][NBUCK];
__device__ unsigned int       g_maxbucket[BATCH];
__device__ int                g_thresh[BATCH];
__device__ unsigned int       g_segovf[BATCH];
__device__ ull                g_cand[BATCH][CAP];
__device__ float4             g_boxes[BATCH * KTOP];
__device__ float              g_areas[BATCH * KTOP];
__device__ unsigned int       g_pcnt[BATCH][KTOP];
__device__ unsigned int       g_padj[BATCH][KTOP][SLOTS];
__device__ unsigned int       g_spill[BATCH][SPILLCAP];
__device__ unsigned int       g_spillcnt[BATCH];
__device__ unsigned int       g_ccnt[BATCH][NCELL];
__device__ unsigned int       g_cells[BATCH][NCELL][CELLCAP];
__device__ unsigned int       g_cellovf[BATCH];
__device__ ull                g_zerobm[BATCH][94];
__device__ ull                g_pairbm[BATCH][94];

/* software grid barrier state (cnt self-resets; gen is monotonic) */
__device__ unsigned int           g_bar_cnt = 0;
__device__ volatile unsigned int  g_bar_gen = 0;

__device__ __forceinline__ void grid_barrier() {
    __syncthreads();
    if (threadIdx.x == 0) {
        __threadfence();
        unsigned int gen = g_bar_gen;
        if (atomicAdd(&g_bar_cnt, 1u) == (unsigned int)(NBLK - 1)) {
            g_bar_cnt = 0;
            __threadfence();
            g_bar_gen = gen + 1;
        } else {
            while (g_bar_gen == gen) { __nanosleep(64); }
        }
        __threadfence();
    }
    __syncthreads();
}

/* order-preserving float -> uint key */
__device__ __forceinline__ unsigned int fkey(float s) {
    unsigned int u = __float_as_uint(s);
    return u ^ ((unsigned int)((int)u >> 31) | 0x80000000u);
}

#define FB_CHUNK 1024   /* pair-fallback chunk (fits 16KB smem buffer) */

/* =================== the single persistent mega-kernel ================== */
__global__ void __launch_bounds__(NTHR, 1)
mega_kernel(const float* __restrict__ probs,
            const float* __restrict__ bbox,
            const float* __restrict__ anchors,
            float* __restrict__ out) {
    __shared__ __align__(16) unsigned char s_raw[16384];
    int tid = threadIdx.x, bid = blockIdx.x;
    size_t gtid    = (size_t)bid * NTHR + tid;
    size_t gstride = (size_t)NBLK * NTHR;

    /* ---------------- P0: clear scratch ---------------- */
    {
        uint4* h4 = (uint4*)&g_hist[0][0];
        size_t n4 = (size_t)BATCH * NBUCK / 4;
        uint4 z4 = make_uint4(0, 0, 0, 0);
        for (size_t i = gtid; i < n4; i += gstride) h4[i] = z4;
        ull* c = &g_cand[0][0];
        for (size_t i = gtid; i < (size_t)BATCH * CAP; i += gstride) c[i] = 0ull;
        unsigned int* pc = &g_pcnt[0][0];
        for (size_t i = gtid; i < (size_t)BATCH * KTOP; i += gstride) pc[i] = 0u;
        unsigned int* cc = &g_ccnt[0][0];
        for (size_t i = gtid; i < (size_t)BATCH * NCELL; i += gstride) cc[i] = 0u;
        ull* zb = &g_zerobm[0][0];
        for (size_t i = gtid; i < (size_t)BATCH * 94 * 2; i += gstride) zb[i] = 0ull;
        if (gtid < BATCH) {
            g_maxbucket[gtid] = 0u; g_spillcnt[gtid] = 0u;
            g_cellovf[gtid] = 0u;  g_segovf[gtid] = 0u;
        }
    }
    grid_barrier();

    /* ---------------- P1: histogram (float4, grid-stride) ---------------- */
    for (int b = 0; b < BATCH; ++b) {
        const float4* p4 = (const float4*)(probs + (size_t)b * NA * 2);
        unsigned int lmax = 0;
        for (size_t v = gtid; v < NA / 2; v += gstride) {
            float4 q = p4[v];
            unsigned int bk1 = fkey(q.y) >> SHIFT;
            unsigned int bk2 = fkey(q.w) >> SHIFT;
            atomicAdd(&g_hist[b][bk1], 1u);
            atomicAdd(&g_hist[b][bk2], 1u);
            lmax = max(lmax, max(bk1, bk2));
        }
        unsigned int red = __reduce_max_sync(0xFFFFFFFFu, lmax);
        if ((tid & 31) == 0) atomicMax(&g_maxbucket[b], red);
    }
    grid_barrier();

    /* ---------------- P2: find threshold bucket (blocks 0..7) ------------ */
    if (bid < BATCH) {
        int b = bid;
        unsigned int* scnt = (unsigned int*)s_raw;            /* 256 u32 */
        __shared__ unsigned int s_running;
        if (tid == 0) s_running = 0;
        __syncthreads();
        int start = (int)g_maxbucket[b];
        for (int cs = start; cs >= 0; cs -= 256) {
            int bk = cs - tid;
            unsigned int c = (bk >= 0) ? g_hist[b][bk] : 0u;
            scnt[tid] = c;
            __syncthreads();
            for (int off = 1; off < 256; off <<= 1) {
                unsigned int v = (tid >= off) ? scnt[tid - off] : 0u;
                __syncthreads();
                scnt[tid] += v;
                __syncthreads();
            }
            unsigned int incl = scnt[tid];
            unsigned int excl = incl - c;
            unsigned int run = s_running;
            if (bk >= 0 && run + excl < KTOP) {
                g_hist[b][bk] = run + excl;
                g_base[b][bk] = run + excl;
                if (c > SEGP || run + excl + c > CAP) g_segovf[b] = 1u;
                if (run + incl >= KTOP) g_thresh[b] = bk;
            }
            __syncthreads();
            if (tid == 0) s_running = run + scnt[255];
            __syncthreads();
            if (s_running >= KTOP) break;
        }
    }
    grid_barrier();

    /* ---------------- P3: compact (float4, grid-stride) ------------------ */
    for (int b = 0; b < BATCH; ++b) {
        int tb = g_thresh[b];
        const float4* p4 = (const float4*)(probs + (size_t)b * NA * 2);
        for (size_t v = gtid; v < NA / 2; v += gstride) {
            float4 q = p4[v];
            unsigned int key1 = fkey(q.y);
            unsigned int key2 = fkey(q.w);
            unsigned int bk1 = key1 >> SHIFT;
            unsigned int bk2 = key2 >> SHIFT;
            if ((int)bk1 >= tb) {
                unsigned int pos = atomicAdd(&g_hist[b][bk1], 1u);
                if (pos < CAP)
                    g_cand[b][pos] = ((ull)key1 << 32) |
                                     (unsigned int)(~(2 * (unsigned int)v));
            }
            if ((int)bk2 >= tb) {
                unsigned int pos = atomicAdd(&g_hist[b][bk2], 1u);
                if (pos < CAP)
                    g_cand[b][pos] = ((ull)key2 << 32) |
                                     (unsigned int)(~(2 * (unsigned int)v + 1));
            }
        }
    }
    grid_barrier();

    /* ---------------- P4: per-bucket segment sort + gated fallback ------- */
    {
        ull* s = (ull*)s_raw;                                 /* 1024 u64 */
        for (int b = 0; b < BATCH; ++b) {
            if (g_segovf[b]) continue;                        /* fallback below */
            int tb = g_thresh[b];
            int mb = (int)g_maxbucket[b];
            for (int bk = tb + bid; bk <= mb; bk += NBLK) {
                unsigned int base = g_base[b][bk];
                unsigned int end  = g_hist[b][bk];
                int n = (int)(end - base);
                if (n <= 1) continue;
                for (int t = tid; t < SEGP; t += NTHR)
                    s[t] = (t < n) ? g_cand[b][base + t] : 0ull;
                __syncthreads();
                for (int k = 2; k <= SEGP; k <<= 1) {
                    for (int j = k >> 1; j > 0; j >>= 1) {
                        for (int t = tid; t < SEGP; t += NTHR) {
                            int ixj = t ^ j;
                            if (ixj > t) {
                                ull x = s[t], y = s[ixj];
                                bool up = ((t & k) == 0);
                                if (up ? (x < y) : (x > y)) { s[t] = y; s[ixj] = x; }
                            }
                        }
                        __syncthreads();
                    }
                }
                for (int t = tid; t < n; t += NTHR)
                    g_cand[b][base + t] = s[t];
                __syncthreads();
            }
        }
        /* never-taken fallback: global-memory bitonic over whole CAP */
        if (bid < BATCH && g_segovf[bid]) {
            int b = bid;
            for (int k = 2; k <= SORTN; k <<= 1) {
                for (int j = k >> 1; j > 0; j >>= 1) {
                    for (int i = tid; i < SORTN; i += NTHR) {
                        int ixj = i ^ j;
                        if (ixj > i) {
                            ull x = g_cand[b][i], y = g_cand[b][ixj];
                            bool up = ((i & k) == 0);
                            if (up ? (x < y) : (x > y)) {
                                g_cand[b][i] = y; g_cand[b][ixj] = x;
                            }
                        }
                    }
                    __syncthreads();
                }
            }
        }
    }
    grid_barrier();

    /* ---------------- P5: gather + decode + cell assign ------------------ */
    for (size_t idx = gtid; idx < (size_t)BATCH * KTOP; idx += gstride) {
        int b = (int)(idx / KTOP);
        int i = (int)(idx % KTOP);
        const float4* anc = (const float4*)(anchors + (size_t)b * NA * 4);
        const float4* dl  = (const float4*)(bbox    + (size_t)b * NA * 4);
        unsigned int idn = ~(unsigned int)(g_cand[b][i]);
        float4 a4 = anc[idn];
        float4 r4 = dl[idn];
        float d0 = __fmul_rn(r4.x, 0.1f);
        float d1 = __fmul_rn(r4.y, 0.1f);
        float d2 = __fmul_rn(r4.z, 0.2f);
        float d3 = __fmul_rn(r4.w, 0.2f);
        float h  = __fsub_rn(a4.z, a4.x);
        float w  = __fsub_rn(a4.w, a4.y);
        float cy = __fadd_rn(__fadd_rn(a4.x, __fmul_rn(0.5f, h)), __fmul_rn(d0, h));
        float cx = __fadd_rn(__fadd_rn(a4.y, __fmul_rn(0.5f, w)), __fmul_rn(d1, w));
        float h2 = __fmul_rn(h, expf(d2));
        float w2 = __fmul_rn(w, expf(d3));
        float y1 = __fsub_rn(cy, __fmul_rn(0.5f, h2));
        float x1 = __fsub_rn(cx, __fmul_rn(0.5f, w2));
        float y2 = __fadd_rn(y1, h2);
        float x2 = __fadd_rn(x1, w2);
        y1 = fminf(fmaxf(y1, 0.0f), 1.0f);
        x1 = fminf(fmaxf(x1, 0.0f), 1.0f);
        y2 = fminf(fmaxf(y2, 0.0f), 1.0f);
        x2 = fminf(fmaxf(x2, 0.0f), 1.0f);
        float area = __fmul_rn(__fsub_rn(y2, y1), __fsub_rn(x2, x1));
        g_boxes[b * KTOP + i] = make_float4(y1, x1, y2, x2);
        g_areas[b * KTOP + i] = area;
        if (area == 0.0f)
            atomicOr(&g_zerobm[b][i >> 6], 1ull << (i & 63));
        int cy0 = min(CELLG - 1, (int)(y1 * CELLG));
        int cx0 = min(CELLG - 1, (int)(x1 * CELLG));
        int cy1 = min(CELLG - 1, (int)(y2 * CELLG));
        int cx1 = min(CELLG - 1, (int)(x2 * CELLG));
        for (int cyy = cy0; cyy <= cy1; ++cyy)
            for (int cxx = cx0; cxx <= cx1; ++cxx) {
                int cell = cyy * CELLG + cxx;
                unsigned int pos = atomicAdd(&g_ccnt[b][cell], 1u);
                if (pos < CELLCAP) g_cells[b][cell][pos] = (unsigned int)i;
                else               g_cellovf[b] = 1u;
            }
    }
    grid_barrier();

    /* ---------------- P6: per-cell pairs + gated brute fallback ---------- */
    {
        float4* sbx = (float4*)s_raw;                           /* 768*16B */
        unsigned short* sid = (unsigned short*)(s_raw + 12288); /* 768*2B  */
        for (int item = bid; item < NCELL * BATCH; item += NBLK) {
            int cell = item & (NCELL - 1);
            int b    = item >> 8;
            int cellx = cell & (CELLG - 1);
            int celly = cell >> 4;
            int n = (int)min(g_ccnt[b][cell], (unsigned int)CELLCAP);
            __syncthreads();
            for (int t = tid; t < n; t += NTHR) {
                unsigned int gi = g_cells[b][cell][t];
                sid[t] = (unsigned short)gi;
                sbx[t] = g_boxes[b * KTOP + gi];
            }
            __syncthreads();
            for (int a = tid; a < n - 1; a += NTHR) {
                float4 A = sbx[a];
                float aA = __fmul_rn(__fsub_rn(A.z, A.x), __fsub_rn(A.w, A.y));
                int idA = (int)sid[a];
                for (int bq = a + 1; bq < n; ++bq) {
                    float4 Bx = sbx[bq];
                    float yy1 = fmaxf(A.x, Bx.x);
                    float xx1 = fmaxf(A.y, Bx.y);
                    float yy2 = fminf(A.z, Bx.z);
                    float xx2 = fminf(A.w, Bx.w);
                    float inter = __fmul_rn(fmaxf(__fsub_rn(yy2, yy1), 0.0f),
                                            fmaxf(__fsub_rn(xx2, xx1), 0.0f));
                    if (inter > 0.0f) {
                        int ccy = min(CELLG - 1, (int)(yy1 * CELLG));
                        int ccx = min(CELLG - 1, (int)(xx1 * CELLG));
                        if (ccy == celly && ccx == cellx) {
                            float aB = __fmul_rn(__fsub_rn(Bx.z, Bx.x),
                                                 __fsub_rn(Bx.w, Bx.y));
                            float uni = __fsub_rn(__fadd_rn(aA, aB), inter);
                            if (uni > 0.0f && !(__fdiv_rn(inter, uni) <= 0.7f)) {
                                int ib = (int)sid[bq];
                                int i = min(idA, ib), j = max(idA, ib);
                                unsigned int pos = atomicAdd(&g_pcnt[b][i], 1u);
                                if (pos == 0u)
                                    atomicOr(&g_pairbm[b][i >> 6],
                                             1ull << (i & 63));
                                if (pos < SLOTS) {
                                    g_padj[b][i][pos] = (unsigned int)j;
                                } else {
                                    unsigned int sp2 =
                                        atomicAdd(&g_spillcnt[b], 1u);
                                    if (sp2 < SPILLCAP)
                                        g_spill[b][sp2] =
                                            ((unsigned int)i << 16) |
                                            (unsigned int)j;
                                }
                            }
                        }
                    }
                }
            }
        }
        __syncthreads();
        /* never-taken brute-force fallback (cell overflow) */
        for (int b = 0; b < BATCH; ++b) {
            if (!g_cellovf[b]) continue;
            int warp = tid >> 5, lane = tid & 31;
            const float4* boxes = g_boxes + b * KTOP;
            const float*  areas = g_areas + b * KTOP;
            for (int rowbase = bid * 64; rowbase < KTOP; rowbase += NBLK * 64) {
                int i0 = rowbase + warp * 8;
                float4 rb[8]; float ra[8];
#pragma unroll
                for (int r = 0; r < 8; ++r) {
                    int i = i0 + r;
                    if (i < KTOP) { rb[r] = boxes[i]; ra[r] = areas[i]; }
                    else { rb[r] = make_float4(0.f, 0.f, 0.f, 0.f); ra[r] = 0.f; }
                }
                for (int chunk = 0; chunk < KTOP; chunk += FB_CHUNK) {
                    int cn = min(FB_CHUNK, KTOP - chunk);
                    __syncthreads();
                    for (int t = tid; t < cn; t += NTHR)
                        sbx[t] = boxes[chunk + t];
                    __syncthreads();
                    if (chunk + cn <= rowbase) continue;
                    int wstart = (i0 + 1 > chunk) ? ((i0 + 1 - chunk) >> 5) : 0;
                    int wend   = (cn + 31) >> 5;
                    for (int wd = wstart; wd < wend; ++wd) {
                        int j = chunk + wd * 32 + lane;
                        float4 cbx = sbx[wd * 32 + lane];
                        float cax = __fmul_rn(__fsub_rn(cbx.z, cbx.x),
                                              __fsub_rn(cbx.w, cbx.y));
                        bool jok = (j < KTOP);
                        unsigned int supmask = 0;
#pragma unroll
                        for (int r = 0; r < 8; ++r) {
                            float yy1 = fmaxf(rb[r].x, cbx.x);
                            float xx1 = fmaxf(rb[r].y, cbx.y);
                            float yy2 = fminf(rb[r].z, cbx.z);
                            float xx2 = fminf(rb[r].w, cbx.w);
                            float inter =
                                __fmul_rn(fmaxf(__fsub_rn(yy2, yy1), 0.0f),
                                          fmaxf(__fsub_rn(xx2, xx1), 0.0f));
                            bool sup = false;
                            if (inter > 0.0f && jok && j > i0 + r) {
                                float uni =
                                    __fsub_rn(__fadd_rn(ra[r], cax), inter);
                                if (uni > 0.0f)
                                    sup = !(__fdiv_rn(inter, uni) <= 0.7f);
                            }
                            supmask |= sup ? (1u << r) : 0u;
                        }
                        if (__any_sync(0xFFFFFFFFu, supmask != 0u)) {
                            while (supmask) {
                                int r = __ffs(supmask) - 1;
                                supmask &= supmask - 1u;
                                int i = i0 + r;
                                unsigned int pos = atomicAdd(&g_pcnt[b][i], 1u);
                                if (pos == 0u)
                                    atomicOr(&g_pairbm[b][i >> 6],
                                             1ull << (i & 63));
                                if (pos < SLOTS) {
                                    g_padj[b][i][pos] = (unsigned int)j;
                                } else {
                                    unsigned int sp2 =
                                        atomicAdd(&g_spillcnt[b], 1u);
                                    if (sp2 < SPILLCAP)
                                        g_spill[b][sp2] =
                                            ((unsigned int)i << 16) |
                                            (unsigned int)j;
                                }
                            }
                        }
                    }
                }
                __syncthreads();
            }
        }
    }
    grid_barrier();

    /* ---------------- P7: sparse serial greedy pass (blocks 0..7) -------- */
    if (bid < BATCH) {
        int b = bid;
        ull* sbm   = (ull*)s_raw;                    /* 94 u64          */
        ull* szero = sbm + 94;                       /* 94 u64          */
        ull* spair = szero + 94;                     /* 94 u64          */
        unsigned char* scnt = (unsigned char*)(spair + 94);   /* 6000  */
        int* s_picks = (int*)(s_raw + 94 * 24 + 6008);        /* 1000  */
        __shared__ int s_ctl[2];

        for (int wu = tid; wu < 94; wu += NTHR) {
            sbm[wu]   = (wu < 93) ? ~0ull : ((1ull << 48) - 1ull);
            szero[wu] = g_zerobm[b][wu];
            spair[wu] = g_pairbm[b][wu];
        }
        for (int i = tid; i < KTOP; i += NTHR) {
            unsigned int c = g_pcnt[b][i];
            scnt[i] = (unsigned char)(c > 255u ? 255u : c);
        }
        __syncthreads();

        if (tid == 0) {
            int sp = 0, fill = -1;
            int sc = (int)g_spillcnt[b];
            if (sc > SPILLCAP) sc = SPILLCAP;
            for (int wu = 0; wu < 94 && sp < PROP && fill < 0; ++wu) {
                ull w = sbm[wu];
                if (!w) continue;
                ull zw = szero[wu];
                ull pw = spair[wu];
                while (w && sp < PROP) {
                    int bx = __ffsll((long long)w) - 1;
                    int i = (wu << 6) + bx;
                    s_picks[sp++] = i;
                    if ((zw >> bx) & 1ull) { fill = i; break; }
                    w &= w - 1ull;
                    if ((pw >> bx) & 1ull) {
                        int n = scnt[i];
                        const unsigned int* adj = g_padj[b][i];
                        int mslots = n < SLOTS ? n : SLOTS;
                        for (int t = 0; t < mslots; ++t) {
                            int j = (int)adj[t];
                            if ((j >> 6) == wu) w &= ~(1ull << (j & 63));
                            else sbm[j >> 6] &= ~(1ull << (j & 63));
                        }
                        if (n > SLOTS) {
                            for (int k = 0; k < sc; ++k) {
                                unsigned int p = g_spill[b][k];
                                if ((int)(p >> 16) == i) {
                                    int j = (int)(p & 0xFFFFu);
                                    if ((j >> 6) == wu)
                                        w &= ~(1ull << (j & 63));
                                    else
                                        sbm[j >> 6] &= ~(1ull << (j & 63));
                                }
                            }
                        }
                    }
                }
            }
            s_ctl[0] = sp;
            s_ctl[1] = fill;
        }
        __syncthreads();
        int step = s_ctl[0];
        int fill = s_ctl[1];

        for (int s2 = step + tid; s2 < PROP; s2 += NTHR) s_picks[s2] = fill;
        __syncthreads();
        const float4* boxes = g_boxes + b * KTOP;
        float4* o = (float4*)out + b * PROP;
        for (int s2 = tid; s2 < PROP; s2 += NTHR) {
            int p = s_picks[s2];
            o[s2] = (p >= 0) ? boxes[p] : make_float4(0.f, 0.f, 0.f, 0.f);
        }
    }
}

/* ---------------- launch ------------------------------------------------ */
extern "C" void kernel_launch(void* const* d_in, const int* in_sizes, int n_in,
                              void* d_out, int out_size) {
    const float* probs   = (const float*)d_in[0];  /* (B, A, 2) */
    const float* bbox    = (const float*)d_in[1];  /* (B, A, 4) */
    const float* anchors = (const float*)d_in[2];  /* (B, A, 4) */
    float* out = (float*)d_out;                    /* (B, 1000, 4) */

    mega_kernel<<<NBLK, NTHR>>>(probs, bbox, anchors, out);
}